// round 2
// baseline (speedup 1.0000x reference)
#include <cuda_runtime.h>
#include <cuda_bf16.h>
#include <math.h>

// Shapes fixed by the reference: B=32, C=512, H=W=64.
#define B_  32
#define C_  512
#define HW_ 4096
#define BC_ (B_ * C_)   // 16384

// Scratch (__device__ globals; no allocation allowed)
__device__ float g_d[BC_];    // per-(b,c) max
__device__ float g_e[BC_];    // per-(b,c) mean
__device__ float g_m[BC_];    // per-row softmax max
__device__ float g_w[BC_];    // per-row (alpha*d + beta*e)/s

// ---------------------------------------------------------------------------
// Kernel 1: per-(b,c) max & mean over each 4096-element plane.
// One 128-thread block per plane; 8 x float4 per thread. Read-BW bound.
// ---------------------------------------------------------------------------
__global__ __launch_bounds__(128) void k_pool(const float* __restrict__ x) {
    const int bc  = blockIdx.x;
    const int tid = threadIdx.x;

    const float4* p = reinterpret_cast<const float4*>(x) + (size_t)bc * (HW_ / 4);

    float mx = -INFINITY;
    float sm = 0.0f;
#pragma unroll
    for (int k = 0; k < 8; ++k) {
        float4 v = p[tid + 128 * k];
        mx = fmaxf(mx, fmaxf(fmaxf(v.x, v.y), fmaxf(v.z, v.w)));
        sm += (v.x + v.y) + (v.z + v.w);
    }

#pragma unroll
    for (int o = 16; o > 0; o >>= 1) {
        mx = fmaxf(mx, __shfl_xor_sync(0xFFFFFFFFu, mx, o));
        sm += __shfl_xor_sync(0xFFFFFFFFu, sm, o);
    }

    __shared__ float smx[4], ssm[4];
    const int w = tid >> 5, l = tid & 31;
    if (l == 0) { smx[w] = mx; ssm[w] = sm; }
    __syncthreads();
    if (tid == 0) {
        float M = smx[0], S = ssm[0];
#pragma unroll
        for (int i = 1; i < 4; ++i) { M = fmaxf(M, smx[i]); S += ssm[i]; }
        g_d[bc] = M;
        g_e[bc] = S * (1.0f / (float)HW_);
    }
}

// ---------------------------------------------------------------------------
// Kernel 2: per-row softmax stats.
//   y[i][j] = d_i*d_j + e_i*e_j ;  m_i = max_j y ;  s_i = sum_j exp(y - m_i)
//   w_i = (alpha*d_i + beta*e_i) / s_i
// Grid: 32 batches x 16 chunks (32 rows each). Block = 256 threads (8 warps),
// warp per row, 4 rows per warp; lane l owns columns {l + 32c, c<16}.
// ---------------------------------------------------------------------------
__global__ __launch_bounds__(256) void k_stats(const float* __restrict__ alpha,
                                               const float* __restrict__ beta) {
    const int b     = blockIdx.x >> 4;
    const int chunk = blockIdx.x & 15;
    const int tid   = threadIdx.x;
    const int lane  = tid & 31;
    const int w     = tid >> 5;

    __shared__ float s_d[C_], s_e[C_];
    for (int i = tid; i < C_; i += 256) {
        s_d[i] = g_d[b * C_ + i];
        s_e[i] = g_e[b * C_ + i];
    }
    __syncthreads();

    float dj[16], ej[16];
#pragma unroll
    for (int c = 0; c < 16; ++c) {
        dj[c] = s_d[lane + 32 * c];
        ej[c] = s_e[lane + 32 * c];
    }

    const float a0 = alpha[0], b0 = beta[0];

    for (int r = w; r < 32; r += 8) {
        const int i = chunk * 32 + r;
        const float di = s_d[i];
        const float ei = s_e[i];

        float t[16];
        float m = -INFINITY;
#pragma unroll
        for (int c = 0; c < 16; ++c) {
            t[c] = fmaf(di, dj[c], ei * ej[c]);
            m = fmaxf(m, t[c]);
        }
#pragma unroll
        for (int o = 16; o > 0; o >>= 1)
            m = fmaxf(m, __shfl_xor_sync(0xFFFFFFFFu, m, o));

        float s = 0.0f;
#pragma unroll
        for (int c = 0; c < 16; ++c)
            s += __expf(t[c] - m);
#pragma unroll
        for (int o = 16; o > 0; o >>= 1)
            s += __shfl_xor_sync(0xFFFFFFFFu, s, o);

        if (lane == 0) {
            g_m[b * C_ + i] = m;
            g_w[b * C_ + i] = fmaf(a0, di, b0 * ei) / s;
        }
    }
}

// ---------------------------------------------------------------------------
// Kernel 3 (fused): per-column weighted exp-sum + broadcast store.
//   f[b,j] = sum_i exp(d_i*d_j + e_i*e_j - m_i) * w_i
// Block = 256 threads (8 warps) handles 8 columns of one batch; warp per
// column: 16 exp-FMA per lane + butterfly sum, then stream the 16KB plane.
// Grid: 32 batches x 64 column-groups = 2048 blocks. Write-BW bound; the
// exp compute hides under the store stream.
// ---------------------------------------------------------------------------
__global__ __launch_bounds__(256) void k_out(float* __restrict__ out) {
    const int blk  = blockIdx.x;
    const int b    = blk >> 6;     // 64 groups of 8 columns per batch
    const int grp  = blk & 63;
    const int tid  = threadIdx.x;
    const int lane = tid & 31;
    const int w    = tid >> 5;

    __shared__ float s_d[C_], s_e[C_], s_m[C_], s_w[C_];
    for (int i = tid; i < C_; i += 256) {
        s_d[i] = g_d[b * C_ + i];
        s_e[i] = g_e[b * C_ + i];
        s_m[i] = g_m[b * C_ + i];
        s_w[i] = g_w[b * C_ + i];
    }
    __syncthreads();

    const int j  = grp * 8 + w;
    const float dj = s_d[j];
    const float ej = s_e[j];

    float acc = 0.0f;
#pragma unroll
    for (int c = 0; c < 16; ++c) {
        const int i = lane + 32 * c;
        acc += __expf(fmaf(s_d[i], dj, s_e[i] * ej) - s_m[i]) * s_w[i];
    }
#pragma unroll
    for (int o = 16; o > 0; o >>= 1)
        acc += __shfl_xor_sync(0xFFFFFFFFu, acc, o);

    const float4 v = make_float4(acc, acc, acc, acc);
    float4* o = reinterpret_cast<float4*>(out) + (size_t)(b * C_ + j) * (HW_ / 4);
#pragma unroll
    for (int k = 0; k < 32; ++k)
        o[lane + 32 * k] = v;
}

extern "C" void kernel_launch(void* const* d_in, const int* in_sizes, int n_in,
                              void* d_out, int out_size) {
    const float* x     = (const float*)d_in[0];
    const float* alpha = (const float*)d_in[1];
    const float* beta  = (const float*)d_in[2];
    float* out = (float*)d_out;

    k_pool<<<BC_, 128>>>(x);
    k_stats<<<B_ * 16, 256>>>(alpha, beta);
    k_out<<<B_ * 64, 256>>>(out);
}